// round 3
// baseline (speedup 1.0000x reference)
#include <cuda_runtime.h>
#include <cuda_bf16.h>

#define NN 50000
#define EE 800000
#define ET 850000   // EE + NN self loops
#define HID 96
#define NEG 0.2f

// ---------------- scratch (no cudaMalloc allowed) ----------------
__device__ float g_h[NN * HID];
__device__ float g_bufA[NN * HID];
__device__ float g_bufB[NN * HID];
__device__ float g_es[NN];
__device__ float g_ed[NN];
__device__ int   g_cnt[NN];
__device__ int   g_rowptr[NN + 1];
__device__ int   g_fill[NN];
__device__ int   g_srcbuf[ET];
__device__ int   g_is64;

// buffer selector: 1 -> g_bufA, 2 -> g_bufB (0 -> external x, handled by caller)
__device__ __forceinline__ float* sel_buf(int s) {
    return (s == 1) ? g_bufA : g_bufB;
}

// edge_index dtype detection: reference asks for int64 but JAX without x64
// silently emits int32. For int64 (values < 2^31) every odd int32 word is 0;
// for int32 random values in [0, 50000) that never happens for 256 samples.
__global__ void detect_kernel(const int* __restrict__ ei32) {
    __shared__ int nz;
    if (threadIdx.x == 0) nz = 0;
    __syncthreads();
    if (ei32[2 * threadIdx.x + 1] != 0) nz = 1;  // benign race, any write works
    __syncthreads();
    if (threadIdx.x == 0) g_is64 = (nz == 0) ? 1 : 0;
}

__device__ __forceinline__ int load_idx(const void* ei, long long pos) {
    if (g_is64) return (int)((const long long*)ei)[pos];
    return ((const int*)ei)[pos];
}

// ---------------- CSR build ----------------
__global__ void zero_cnt_kernel() {
    int i = blockIdx.x * blockDim.x + threadIdx.x;
    if (i < NN) g_cnt[i] = 0;
}

__global__ void hist_kernel(const void* __restrict__ ei) {
    int j = blockIdx.x * blockDim.x + threadIdx.x;
    if (j >= ET) return;
    int dst = (j < EE) ? load_idx(ei, (long long)EE + j) : (j - EE);
    atomicAdd(&g_cnt[dst], 1);
}

__global__ void scan_kernel() {
    __shared__ int sh[1024];
    const int C = (NN + 1023) / 1024;   // 49
    int t = threadIdx.x;
    int base = t * C;
    int sum = 0;
    for (int i = 0; i < C; i++) {
        int idx = base + i;
        if (idx < NN) sum += g_cnt[idx];
    }
    sh[t] = sum;
    __syncthreads();
    // Hillis-Steele inclusive scan
    for (int off = 1; off < 1024; off <<= 1) {
        int v = sh[t];
        int add = (t >= off) ? sh[t - off] : 0;
        __syncthreads();
        sh[t] = v + add;
        __syncthreads();
    }
    int run = sh[t] - sum;   // exclusive prefix for this thread's chunk
    for (int i = 0; i < C; i++) {
        int idx = base + i;
        if (idx < NN) {
            g_rowptr[idx] = run;
            g_fill[idx]   = run;
            run += g_cnt[idx];
        }
    }
    if (t == 1023) g_rowptr[NN] = ET;
}

__global__ void scatter_kernel(const void* __restrict__ ei) {
    int j = blockIdx.x * blockDim.x + threadIdx.x;
    if (j >= ET) return;
    int src, dst;
    if (j < EE) {
        src = load_idx(ei, j);
        dst = load_idx(ei, (long long)EE + j);
    } else {
        src = dst = j - EE;
    }
    int pos = atomicAdd(&g_fill[dst], 1);
    g_srcbuf[pos] = src;
}

// ---------------- GEMM: g_h = in @ W  (4 nodes per block, 96 threads) ----------------
// in_sel: 0 -> use x param, 1 -> g_bufA, 2 -> g_bufB
template <int IN>
__global__ void gemm_kernel(const float* __restrict__ x, int in_sel,
                            const float* __restrict__ W) {
    __shared__ float xs[4][IN];
    const float* in = (in_sel == 0) ? x : sel_buf(in_sel);
    int nb = blockIdx.x * 4;
    int o  = threadIdx.x;   // 0..95
    for (int idx = threadIdx.x; idx < 4 * IN; idx += HID) {
        int r = idx / IN, c = idx % IN;
        xs[r][c] = in[(nb + r) * IN + c];
    }
    __syncthreads();
    float a0 = 0.f, a1 = 0.f, a2 = 0.f, a3 = 0.f;
#pragma unroll
    for (int k = 0; k < IN; k++) {
        float w = W[k * HID + o];
        a0 += xs[0][k] * w;
        a1 += xs[1][k] * w;
        a2 += xs[2][k] * w;
        a3 += xs[3][k] * w;
    }
    g_h[(nb + 0) * HID + o] = a0;
    g_h[(nb + 1) * HID + o] = a1;
    g_h[(nb + 2) * HID + o] = a2;
    g_h[(nb + 3) * HID + o] = a3;
}

// ---------------- per-node attention logits: es = h.a_s, ed = h.a_d ----------------
__global__ void esed_kernel(const float* __restrict__ as, const float* __restrict__ ad) {
    int node = (blockIdx.x * blockDim.x + threadIdx.x) >> 5;
    int lane = threadIdx.x & 31;
    if (node >= NN) return;
    const float* hp = g_h + node * HID;
    float vs = 0.f, vd = 0.f;
#pragma unroll
    for (int i = lane; i < HID; i += 32) {
        float hv = hp[i];
        vs += hv * as[i];
        vd += hv * ad[i];
    }
#pragma unroll
    for (int off = 16; off; off >>= 1) {
        vs += __shfl_xor_sync(0xFFFFFFFFu, vs, off);
        vd += __shfl_xor_sync(0xFFFFFFFFu, vd, off);
    }
    if (lane == 0) { g_es[node] = vs; g_ed[node] = vd; }
}

// ---------------- aggregation: one warp per destination node ----------------
template <bool RESID>
__global__ void agg_kernel(const float* __restrict__ b, int resid_sel, int out_sel) {
    int node = (blockIdx.x * blockDim.x + threadIdx.x) >> 5;
    int lane = threadIdx.x & 31;
    if (node >= NN) return;
    int beg = g_rowptr[node], end = g_rowptr[node + 1];
    float edst = g_ed[node];

    float m = -1e30f;
    for (int j = beg + lane; j < end; j += 32) {
        float e = g_es[g_srcbuf[j]] + edst;
        e = (e > 0.f) ? e : NEG * e;
        m = fmaxf(m, e);
    }
#pragma unroll
    for (int off = 16; off; off >>= 1)
        m = fmaxf(m, __shfl_xor_sync(0xFFFFFFFFu, m, off));

    float a0 = 0.f, a1 = 0.f, a2 = 0.f, ssum = 0.f;
#pragma unroll 4
    for (int j = beg; j < end; j++) {
        int s = g_srcbuf[j];                 // broadcast load
        float e = g_es[s] + edst;            // broadcast load
        e = (e > 0.f) ? e : NEG * e;
        float ex = __expf(e - m);
        const float* hp = g_h + s * HID;
        ssum += ex;
        a0 += ex * hp[lane];
        a1 += ex * hp[lane + 32];
        a2 += ex * hp[lane + 64];
    }
    float inv = 1.f / ssum;
    float o0 = a0 * inv + b[lane];
    float o1 = a1 * inv + b[lane + 32];
    float o2 = a2 * inv + b[lane + 64];
    if (RESID) {
        const float* rp = sel_buf(resid_sel) + node * HID;
        o0 += rp[lane]; o1 += rp[lane + 32]; o2 += rp[lane + 64];
    }
    o0 = fmaxf(o0, 0.f); o1 = fmaxf(o1, 0.f); o2 = fmaxf(o2, 0.f);
    float* op = sel_buf(out_sel) + node * HID;
    op[lane] = o0; op[lane + 32] = o1; op[lane + 64] = o2;
}

// ---------------- final layer (out dim = 1) ----------------
__global__ void finalh_kernel(int in_sel, const float* __restrict__ Wf,
                              const float* __restrict__ asf, const float* __restrict__ adf) {
    int node = (blockIdx.x * blockDim.x + threadIdx.x) >> 5;
    int lane = threadIdx.x & 31;
    if (node >= NN) return;
    const float* xp = sel_buf(in_sel) + node * HID;
    float v = 0.f;
#pragma unroll
    for (int i = lane; i < HID; i += 32) v += xp[i] * Wf[i];
#pragma unroll
    for (int off = 16; off; off >>= 1)
        v += __shfl_xor_sync(0xFFFFFFFFu, v, off);
    if (lane == 0) {
        g_h[node]  = v;            // reuse g_h[0..NN) as hf
        g_es[node] = v * asf[0];
        g_ed[node] = v * adf[0];
    }
}

__global__ void fagg_kernel(const float* __restrict__ bf, float* __restrict__ out) {
    int node = (blockIdx.x * blockDim.x + threadIdx.x) >> 5;
    int lane = threadIdx.x & 31;
    if (node >= NN) return;
    int beg = g_rowptr[node], end = g_rowptr[node + 1];
    float edst = g_ed[node];

    float m = -1e30f;
    for (int j = beg + lane; j < end; j += 32) {
        float e = g_es[g_srcbuf[j]] + edst;
        e = (e > 0.f) ? e : NEG * e;
        m = fmaxf(m, e);
    }
#pragma unroll
    for (int off = 16; off; off >>= 1)
        m = fmaxf(m, __shfl_xor_sync(0xFFFFFFFFu, m, off));

    float ssum = 0.f, wsum = 0.f;
    for (int j = beg + lane; j < end; j += 32) {
        int s = g_srcbuf[j];
        float e = g_es[s] + edst;
        e = (e > 0.f) ? e : NEG * e;
        float ex = __expf(e - m);
        ssum += ex;
        wsum += ex * g_h[s];
    }
#pragma unroll
    for (int off = 16; off; off >>= 1) {
        ssum += __shfl_xor_sync(0xFFFFFFFFu, ssum, off);
        wsum += __shfl_xor_sync(0xFFFFFFFFu, wsum, off);
    }
    if (lane == 0) out[node] = wsum / ssum + bf[0];
}

// ---------------- launch ----------------
extern "C" void kernel_launch(void* const* d_in, const int* in_sizes, int n_in,
                              void* d_out, int out_size) {
    const float* x   = (const float*)d_in[0];
    const void*  ei  = d_in[1];
    const float* W0  = (const float*)d_in[3];
    const float* as0 = (const float*)d_in[4];
    const float* ad0 = (const float*)d_in[5];
    const float* b0  = (const float*)d_in[6];
    const float* W1  = (const float*)d_in[7];
    const float* as1 = (const float*)d_in[8];
    const float* ad1 = (const float*)d_in[9];
    const float* b1  = (const float*)d_in[10];
    const float* W2  = (const float*)d_in[11];
    const float* as2 = (const float*)d_in[12];
    const float* ad2 = (const float*)d_in[13];
    const float* b2  = (const float*)d_in[14];
    const float* Wf  = (const float*)d_in[15];
    const float* asf = (const float*)d_in[16];
    const float* adf = (const float*)d_in[17];
    const float* bf  = (const float*)d_in[18];
    float* out = (float*)d_out;

    const int TPB = 256;
    const int edge_blocks = (ET + TPB - 1) / TPB;
    const int node_warp_blocks = (NN * 32 + TPB - 1) / TPB;   // 1 warp per node

    // dtype probe + CSR build (sort edges by dst, include self loops)
    detect_kernel<<<1, 256>>>((const int*)ei);
    zero_cnt_kernel<<<(NN + TPB - 1) / TPB, TPB>>>();
    hist_kernel<<<edge_blocks, TPB>>>(ei);
    scan_kernel<<<1, 1024>>>();
    scatter_kernel<<<edge_blocks, TPB>>>(ei);

    // Layer 0: 32 -> 96, no residual, relu.  out -> bufA
    gemm_kernel<32><<<NN / 4, HID>>>(x, 0, W0);
    esed_kernel<<<node_warp_blocks, TPB>>>(as0, ad0);
    agg_kernel<false><<<node_warp_blocks, TPB>>>(b0, 0, 1);

    // Layer 1: 96 -> 96, residual(bufA), relu.  out -> bufB
    gemm_kernel<HID><<<NN / 4, HID>>>(nullptr, 1, W1);
    esed_kernel<<<node_warp_blocks, TPB>>>(as1, ad1);
    agg_kernel<true><<<node_warp_blocks, TPB>>>(b1, 1, 2);

    // Layer 2: 96 -> 96, residual(bufB), relu.  out -> bufA
    gemm_kernel<HID><<<NN / 4, HID>>>(nullptr, 2, W2);
    esed_kernel<<<node_warp_blocks, TPB>>>(as2, ad2);
    agg_kernel<true><<<node_warp_blocks, TPB>>>(b2, 2, 1);

    // Final layer: 96 -> 1 (input bufA)
    finalh_kernel<<<node_warp_blocks, TPB>>>(1, Wf, asf, adf);
    fagg_kernel<<<node_warp_blocks, TPB>>>(bf, out);
}

// round 4
// speedup vs baseline: 1.2985x; 1.2985x over previous
#include <cuda_runtime.h>
#include <cuda_bf16.h>

#define NN 50000
#define EE 800000
#define ET 850000   // EE + NN self loops
#define HID 96
#define NEG 0.2f

#define SCAN_TPB 256
#define SCAN_BLOCKS ((NN + SCAN_TPB - 1) / SCAN_TPB)   // 196

// ---------------- scratch (no cudaMalloc allowed) ----------------
__device__ float g_h[NN * HID];
__device__ float g_bufA[NN * HID];
__device__ float g_bufB[NN * HID];
__device__ float g_es[NN];
__device__ float g_ed[NN];
__device__ float g_hf[NN];
__device__ float g_esf[NN];
__device__ float g_edf[NN];
__device__ int   g_cnt[NN];
__device__ int   g_rowptr[NN + 1];
__device__ int   g_fill[NN];
__device__ int   g_srcbuf[ET];
__device__ int   g_bsum[SCAN_BLOCKS];
__device__ int   g_is64;

// buffer selector: 1 -> g_bufA, 2 -> g_bufB
__device__ __forceinline__ float* sel_buf(int s) {
    return (s == 1) ? g_bufA : g_bufB;
}

// ---------------- init: zero counters + dtype probe ----------------
// edge_index dtype: reference asks int64 but JAX without x64 emits int32.
// For int64 (values < 2^31) every odd int32 word is 0; for int32 random
// values in [0, 50000) that never happens across 256 samples.
__global__ void init_kernel(const int* __restrict__ ei32) {
    int i = blockIdx.x * blockDim.x + threadIdx.x;
    if (i < NN) g_cnt[i] = 0;
    if (blockIdx.x == 0) {
        __shared__ int nz;
        if (threadIdx.x == 0) nz = 0;
        __syncthreads();
        if (ei32[2 * threadIdx.x + 1] != 0) nz = 1;  // benign race
        __syncthreads();
        if (threadIdx.x == 0) g_is64 = (nz == 0) ? 1 : 0;
    }
}

__device__ __forceinline__ int load_idx(const void* ei, long long pos) {
    if (g_is64) return (int)((const long long*)ei)[pos];
    return ((const int*)ei)[pos];
}

// ---------------- CSR build ----------------
__global__ void hist_kernel(const void* __restrict__ ei) {
    int j = blockIdx.x * blockDim.x + threadIdx.x;
    if (j >= ET) return;
    int dst = (j < EE) ? load_idx(ei, (long long)EE + j) : (j - EE);
    atomicAdd(&g_cnt[dst], 1);
}

// per-block sums of g_cnt
__global__ void bsum_kernel() {
    __shared__ int sh[SCAN_TPB];
    int t = threadIdx.x;
    int i = blockIdx.x * SCAN_TPB + t;
    sh[t] = (i < NN) ? g_cnt[i] : 0;
    __syncthreads();
#pragma unroll
    for (int off = SCAN_TPB / 2; off > 0; off >>= 1) {
        if (t < off) sh[t] += sh[t + off];
        __syncthreads();
    }
    if (t == 0) g_bsum[blockIdx.x] = sh[0];
}

// each block: offset = sum of bsums before it, then 256-wide inclusive scan
__global__ void scanout_kernel() {
    __shared__ int shoff[SCAN_TPB];
    __shared__ int sh[SCAN_TPB];
    int t = threadIdx.x;
    shoff[t] = (t < blockIdx.x && t < SCAN_BLOCKS) ? g_bsum[t] : 0;
    int i = blockIdx.x * SCAN_TPB + t;
    int c = (i < NN) ? g_cnt[i] : 0;
    sh[t] = c;
    __syncthreads();
#pragma unroll
    for (int off = SCAN_TPB / 2; off > 0; off >>= 1) {
        if (t < off) shoff[t] += shoff[t + off];
        __syncthreads();
    }
    // Hillis-Steele inclusive scan of sh
#pragma unroll
    for (int off = 1; off < SCAN_TPB; off <<= 1) {
        int v = sh[t];
        int add = (t >= off) ? sh[t - off] : 0;
        __syncthreads();
        sh[t] = v + add;
        __syncthreads();
    }
    int excl = sh[t] - c + shoff[0];
    if (i < NN) {
        g_rowptr[i] = excl;
        g_fill[i]   = excl;
    }
    if (i == NN - 1) g_rowptr[NN] = ET;
}

__global__ void scatter_kernel(const void* __restrict__ ei) {
    int j = blockIdx.x * blockDim.x + threadIdx.x;
    if (j >= ET) return;
    int src, dst;
    if (j < EE) {
        src = load_idx(ei, j);
        dst = load_idx(ei, (long long)EE + j);
    } else {
        src = dst = j - EE;
    }
    int pos = atomicAdd(&g_fill[dst], 1);
    g_srcbuf[pos] = src;
}

// ---------------- GEMM: g_h = in @ W  (4 nodes per block, 96 threads) ----------------
template <int IN>
__global__ void gemm_kernel(const float* __restrict__ x, int in_sel,
                            const float* __restrict__ W) {
    __shared__ float xs[4][IN];
    const float* in = (in_sel == 0) ? x : sel_buf(in_sel);
    int nb = blockIdx.x * 4;
    int o  = threadIdx.x;   // 0..95
    for (int idx = threadIdx.x; idx < 4 * IN; idx += HID) {
        int r = idx / IN, c = idx % IN;
        xs[r][c] = in[(nb + r) * IN + c];
    }
    __syncthreads();
    float a0 = 0.f, a1 = 0.f, a2 = 0.f, a3 = 0.f;
#pragma unroll
    for (int k = 0; k < IN; k++) {
        float w = W[k * HID + o];
        a0 += xs[0][k] * w;
        a1 += xs[1][k] * w;
        a2 += xs[2][k] * w;
        a3 += xs[3][k] * w;
    }
    g_h[(nb + 0) * HID + o] = a0;
    g_h[(nb + 1) * HID + o] = a1;
    g_h[(nb + 2) * HID + o] = a2;
    g_h[(nb + 3) * HID + o] = a3;
}

// ---------------- per-node attention logits: es = h.a_s, ed = h.a_d ----------------
__global__ void esed_kernel(const float* __restrict__ as, const float* __restrict__ ad) {
    int node = (blockIdx.x * blockDim.x + threadIdx.x) >> 5;
    int lane = threadIdx.x & 31;
    if (node >= NN) return;
    const float* hp = g_h + node * HID;
    float vs = 0.f, vd = 0.f;
#pragma unroll
    for (int i = lane; i < HID; i += 32) {
        float hv = hp[i];
        vs += hv * as[i];
        vd += hv * ad[i];
    }
#pragma unroll
    for (int off = 16; off; off >>= 1) {
        vs += __shfl_xor_sync(0xFFFFFFFFu, vs, off);
        vd += __shfl_xor_sync(0xFFFFFFFFu, vd, off);
    }
    if (lane == 0) { g_es[node] = vs; g_ed[node] = vd; }
}

// ---------------- aggregation: one warp per destination node ----------------
// FINAL: fuse the 96->1 projection of the last layer into the epilogue,
// writing g_hf / g_esf / g_edf (separate arrays: g_h/g_es still being read).
template <bool RESID, bool FINAL>
__global__ void agg_kernel(const float* __restrict__ b, int resid_sel, int out_sel,
                           const float* __restrict__ Wf,
                           const float* __restrict__ asf,
                           const float* __restrict__ adf) {
    int node = (blockIdx.x * blockDim.x + threadIdx.x) >> 5;
    int lane = threadIdx.x & 31;
    if (node >= NN) return;
    int beg = g_rowptr[node], end = g_rowptr[node + 1];
    float edst = g_ed[node];

    float m = -1e30f;
    for (int j = beg + lane; j < end; j += 32) {
        float e = g_es[g_srcbuf[j]] + edst;
        e = (e > 0.f) ? e : NEG * e;
        m = fmaxf(m, e);
    }
#pragma unroll
    for (int off = 16; off; off >>= 1)
        m = fmaxf(m, __shfl_xor_sync(0xFFFFFFFFu, m, off));

    float a0 = 0.f, a1 = 0.f, a2 = 0.f, ssum = 0.f;
#pragma unroll 4
    for (int j = beg; j < end; j++) {
        int s = g_srcbuf[j];                 // broadcast load
        float e = g_es[s] + edst;            // broadcast load
        e = (e > 0.f) ? e : NEG * e;
        float ex = __expf(e - m);
        const float* hp = g_h + s * HID;
        ssum += ex;
        a0 += ex * hp[lane];
        a1 += ex * hp[lane + 32];
        a2 += ex * hp[lane + 64];
    }
    float inv = 1.f / ssum;
    float o0 = a0 * inv + b[lane];
    float o1 = a1 * inv + b[lane + 32];
    float o2 = a2 * inv + b[lane + 64];
    if (RESID) {
        const float* rp = sel_buf(resid_sel) + node * HID;
        o0 += rp[lane]; o1 += rp[lane + 32]; o2 += rp[lane + 64];
    }
    o0 = fmaxf(o0, 0.f); o1 = fmaxf(o1, 0.f); o2 = fmaxf(o2, 0.f);
    if (FINAL) {
        // fused 96->1 projection: hf = relu_out . Wf
        float v = o0 * Wf[lane] + o1 * Wf[lane + 32] + o2 * Wf[lane + 64];
#pragma unroll
        for (int off = 16; off; off >>= 1)
            v += __shfl_xor_sync(0xFFFFFFFFu, v, off);
        if (lane == 0) {
            g_hf[node]  = v;
            g_esf[node] = v * asf[0];
            g_edf[node] = v * adf[0];
        }
    } else {
        float* op = sel_buf(out_sel) + node * HID;
        op[lane] = o0; op[lane + 32] = o1; op[lane + 64] = o2;
    }
}

// ---------------- final aggregation (out dim = 1) ----------------
__global__ void fagg_kernel(const float* __restrict__ bf, float* __restrict__ out) {
    int node = (blockIdx.x * blockDim.x + threadIdx.x) >> 5;
    int lane = threadIdx.x & 31;
    if (node >= NN) return;
    int beg = g_rowptr[node], end = g_rowptr[node + 1];
    float edst = g_edf[node];

    float m = -1e30f;
    for (int j = beg + lane; j < end; j += 32) {
        float e = g_esf[g_srcbuf[j]] + edst;
        e = (e > 0.f) ? e : NEG * e;
        m = fmaxf(m, e);
    }
#pragma unroll
    for (int off = 16; off; off >>= 1)
        m = fmaxf(m, __shfl_xor_sync(0xFFFFFFFFu, m, off));

    float ssum = 0.f, wsum = 0.f;
    for (int j = beg + lane; j < end; j += 32) {
        int s = g_srcbuf[j];
        float e = g_esf[s] + edst;
        e = (e > 0.f) ? e : NEG * e;
        float ex = __expf(e - m);
        ssum += ex;
        wsum += ex * g_hf[s];
    }
#pragma unroll
    for (int off = 16; off; off >>= 1) {
        ssum += __shfl_xor_sync(0xFFFFFFFFu, ssum, off);
        wsum += __shfl_xor_sync(0xFFFFFFFFu, wsum, off);
    }
    if (lane == 0) out[node] = wsum / ssum + bf[0];
}

// ---------------- launch ----------------
extern "C" void kernel_launch(void* const* d_in, const int* in_sizes, int n_in,
                              void* d_out, int out_size) {
    const float* x   = (const float*)d_in[0];
    const void*  ei  = d_in[1];
    const float* W0  = (const float*)d_in[3];
    const float* as0 = (const float*)d_in[4];
    const float* ad0 = (const float*)d_in[5];
    const float* b0  = (const float*)d_in[6];
    const float* W1  = (const float*)d_in[7];
    const float* as1 = (const float*)d_in[8];
    const float* ad1 = (const float*)d_in[9];
    const float* b1  = (const float*)d_in[10];
    const float* W2  = (const float*)d_in[11];
    const float* as2 = (const float*)d_in[12];
    const float* ad2 = (const float*)d_in[13];
    const float* b2  = (const float*)d_in[14];
    const float* Wf  = (const float*)d_in[15];
    const float* asf = (const float*)d_in[16];
    const float* adf = (const float*)d_in[17];
    const float* bf  = (const float*)d_in[18];
    float* out = (float*)d_out;

    const int TPB = 256;
    const int edge_blocks = (ET + TPB - 1) / TPB;
    const int node_warp_blocks = (NN * 32 + TPB - 1) / TPB;   // 1 warp per node

    // CSR build (sort edges by dst, include self loops)
    init_kernel<<<SCAN_BLOCKS, SCAN_TPB>>>((const int*)ei);
    hist_kernel<<<edge_blocks, TPB>>>(ei);
    bsum_kernel<<<SCAN_BLOCKS, SCAN_TPB>>>();
    scanout_kernel<<<SCAN_BLOCKS, SCAN_TPB>>>();
    scatter_kernel<<<edge_blocks, TPB>>>(ei);

    // Layer 0: 32 -> 96, no residual, relu.  out -> bufA
    gemm_kernel<32><<<NN / 4, HID>>>(x, 0, W0);
    esed_kernel<<<node_warp_blocks, TPB>>>(as0, ad0);
    agg_kernel<false, false><<<node_warp_blocks, TPB>>>(b0, 0, 1, nullptr, nullptr, nullptr);

    // Layer 1: 96 -> 96, residual(bufA), relu.  out -> bufB
    gemm_kernel<HID><<<NN / 4, HID>>>(nullptr, 1, W1);
    esed_kernel<<<node_warp_blocks, TPB>>>(as1, ad1);
    agg_kernel<true, false><<<node_warp_blocks, TPB>>>(b1, 1, 2, nullptr, nullptr, nullptr);

    // Layer 2: 96 -> 96, residual(bufB), relu, fused final 96->1 projection
    gemm_kernel<HID><<<NN / 4, HID>>>(nullptr, 2, W2);
    esed_kernel<<<node_warp_blocks, TPB>>>(as2, ad2);
    agg_kernel<true, true><<<node_warp_blocks, TPB>>>(b2, 2, 0, Wf, asf, adf);

    // Final layer aggregation (dim 1)
    fagg_kernel<<<node_warp_blocks, TPB>>>(bf, out);
}